// round 2
// baseline (speedup 1.0000x reference)
#include <cuda_runtime.h>

#define B_TOTAL 4096
#define T_STEPS 256
#define IN_DIM 16
#define H1 64
#define G1 256            // 4*H1 gate rows
#define BPB 2             // batches per block
#define NGATE 512         // 2 threads per gate row
#define NTHREADS 544      // 16 gate warps + 1 layer2 warp

using u64 = unsigned long long;

__device__ __forceinline__ u64 pack2(float x, float y) {
    u64 r; asm("mov.b64 %0, {%1, %2};" : "=l"(r) : "f"(x), "f"(y)); return r;
}
__device__ __forceinline__ void unpack2(u64 v, float &x, float &y) {
    asm("mov.b64 {%0, %1}, %2;" : "=f"(x), "=f"(y) : "l"(v));
}
__device__ __forceinline__ u64 ffma2(u64 a, u64 b, u64 c) {
    u64 d; asm("fma.rn.f32x2 %0, %1, %2, %3;" : "=l"(d) : "l"(a), "l"(b), "l"(c)); return d;
}
__device__ __forceinline__ float ex2f(float x){ float y; asm("ex2.approx.f32 %0, %1;" : "=f"(y) : "f"(x)); return y; }
__device__ __forceinline__ float rcpf(float x){ float y; asm("rcp.approx.f32 %0, %1;" : "=f"(y) : "f"(x)); return y; }
__device__ __forceinline__ float sigmoid_f(float x){ return rcpf(1.0f + ex2f(-1.4426950408889634f * x)); }
__device__ __forceinline__ float tanh_f(float x){ return 2.0f * rcpf(1.0f + ex2f(-2.8853900817779268f * x)) - 1.0f; }

__global__ void __launch_bounds__(NTHREADS)
lstm2_fused_kernel(
    const float* __restrict__ x,
    const float* __restrict__ w_ih1, const float* __restrict__ w_hh1,
    const float* __restrict__ b_ih1, const float* __restrict__ b_hh1,
    const float* __restrict__ w_ih2, const float* __restrict__ w_hh2,
    const float* __restrict__ b_ih2, const float* __restrict__ b_hh2,
    const float* __restrict__ fc_w,  const float* __restrict__ fc_b,
    float* __restrict__ out)
{
    __shared__ float xs[BPB][T_STEPS][IN_DIM];    // 32 KB input window
    __shared__ float h1buf[2][BPB][H1];           // double-buffered layer1 hidden
    __shared__ float gates_s[BPB][G1];            // activated gates
    __shared__ float l2c[12];                     // layer2 consts

    const int tid = threadIdx.x;
    const int b0  = blockIdx.x * BPB;

    // ---- prologue: stage x into smem (coalesced float4) ----
    {
        const int per_b = T_STEPS * IN_DIM / 4;   // 1024 float4 per batch
        float4* xsd = (float4*)&xs[0][0][0];
        for (int i = tid; i < BPB * per_b; i += NTHREADS) {
            int bb = i / per_b;
            int r  = i - bb * per_b;
            xsd[i] = ((const float4*)(x + (size_t)(b0 + bb) * T_STEPS * IN_DIM))[r];
        }
    }
    if (tid < BPB * H1) h1buf[0][tid >> 6][tid & 63] = 0.0f;
    if (tid == 0) {
        #pragma unroll
        for (int g = 0; g < 4; ++g) {
            l2c[g]     = b_ih2[g] + b_hh2[g];
            l2c[4 + g] = w_hh2[g];
        }
        l2c[8] = fc_w[0];
        l2c[9] = fc_b[0];
    }

    // ---- gate-thread register state: half a gate row per thread ----
    // tid < 512: row = tid>>1, half = tid&1
    //   half 0: x[0:8],  h[0:32];  half 1: x[8:16], h[32:64]
    const int row  = tid >> 1;
    const int half = tid & 1;
    u64 wih[4];        // 8 floats
    u64 whh[16];       // 32 floats
    float bias = 0.0f;
    float c_state = 0.0f;

    if (tid < NGATE) {
        const ulonglong2* wi = (const ulonglong2*)(w_ih1 + row * IN_DIM + half * 8);
        #pragma unroll
        for (int k = 0; k < 2; ++k) { ulonglong2 v = wi[k]; wih[2*k] = v.x; wih[2*k+1] = v.y; }
        const ulonglong2* wh = (const ulonglong2*)(w_hh1 + row * H1 + half * 32);
        #pragma unroll
        for (int k = 0; k < 8; ++k) { ulonglong2 v = wh[k]; whh[2*k] = v.x; whh[2*k+1] = v.y; }
        if (half == 0) bias = b_ih1[row] + b_hh1[row];
    }

    // ---- layer2 warp state (tid >= 512) ----
    const int lane = tid - NGATE;
    const int gg = (lane >= 0) ? (lane >> 3) : 0;
    const int pp = (lane >= 0) ? (lane & 7) : 0;
    float w2[8];
    float h2s[BPB], c2s[BPB];
    #pragma unroll
    for (int bb = 0; bb < BPB; ++bb) { h2s[bb] = 0.0f; c2s[bb] = 0.0f; }
    if (tid >= NGATE) {
        #pragma unroll
        for (int e = 0; e < 8; ++e) w2[e] = w_ih2[gg * H1 + pp * 8 + e];
    } else {
        #pragma unroll
        for (int e = 0; e < 8; ++e) w2[e] = 0.0f;
    }

    auto layer2_step = [&](int tt, int curbuf) {
        #pragma unroll
        for (int bb = 0; bb < BPB; ++bb) {
            const float* hr = &h1buf[curbuf][bb][0];
            float p = 0.0f;
            #pragma unroll
            for (int e = 0; e < 8; ++e) p = fmaf(w2[e], hr[pp * 8 + e], p);
            p += __shfl_xor_sync(0xffffffffu, p, 1);
            p += __shfl_xor_sync(0xffffffffu, p, 2);
            p += __shfl_xor_sync(0xffffffffu, p, 4);
            float s0 = __shfl_sync(0xffffffffu, p, 0);
            float s1 = __shfl_sync(0xffffffffu, p, 8);
            float s2 = __shfl_sync(0xffffffffu, p, 16);
            float s3 = __shfl_sync(0xffffffffu, p, 24);
            if (lane == 0) {
                float hp = h2s[bb];
                float i2 = sigmoid_f(s0 + l2c[0] + l2c[4] * hp);
                float f2 = sigmoid_f(s1 + l2c[1] + l2c[5] * hp);
                float g2 = tanh_f  (s2 + l2c[2] + l2c[6] * hp);
                float o2 = sigmoid_f(s3 + l2c[3] + l2c[7] * hp);
                float c2 = fmaf(f2, c2s[bb], i2 * g2);
                c2s[bb] = c2;
                float h2 = o2 * tanh_f(c2);
                h2s[bb] = h2;
                out[(size_t)(b0 + bb) * T_STEPS + tt] = fmaf(h2, l2c[8], l2c[9]);
            }
        }
    };

    // ---- main recurrence ----
    int cur = 0;
    for (int t = 0; t < T_STEPS; ++t) {
        __syncthreads();   // h1buf[cur] ready; gates_s free
        if (tid < NGATE) {
            const ulonglong2* x0 = (const ulonglong2*)&xs[0][t][half * 8];
            const ulonglong2* x1 = (const ulonglong2*)&xs[1][t][half * 8];
            u64 a0 = pack2(bias, 0.0f);
            u64 a1 = pack2(bias, 0.0f);
            #pragma unroll
            for (int k = 0; k < 2; ++k) {
                ulonglong2 v0 = x0[k], v1 = x1[k];
                a0 = ffma2(wih[2*k],   v0.x, a0);  a1 = ffma2(wih[2*k],   v1.x, a1);
                a0 = ffma2(wih[2*k+1], v0.y, a0);  a1 = ffma2(wih[2*k+1], v1.y, a1);
            }
            const ulonglong2* h0p = (const ulonglong2*)&h1buf[cur][0][half * 32];
            const ulonglong2* h1p = (const ulonglong2*)&h1buf[cur][1][half * 32];
            #pragma unroll
            for (int k = 0; k < 8; ++k) {
                ulonglong2 v0 = h0p[k], v1 = h1p[k];
                a0 = ffma2(whh[2*k],   v0.x, a0);  a1 = ffma2(whh[2*k],   v1.x, a1);
                a0 = ffma2(whh[2*k+1], v0.y, a0);  a1 = ffma2(whh[2*k+1], v1.y, a1);
            }
            float g0x, g0y, g1x, g1y;
            unpack2(a0, g0x, g0y);
            unpack2(a1, g1x, g1y);
            float sa = g0x + g0y;
            float sb = g1x + g1y;
            // combine the two halves of the row (pair lanes 2i, 2i+1)
            sa += __shfl_xor_sync(0xffffffffu, sa, 1);
            sb += __shfl_xor_sync(0xffffffffu, sb, 1);
            int wtype = row >> 6;           // uniform per warp (16 rows/warp within a 64-row gate block)
            float ga, gb;
            if (wtype == 2) { ga = tanh_f(sa);    gb = tanh_f(sb); }
            else            { ga = sigmoid_f(sa); gb = sigmoid_f(sb); }
            if (half == 0) {
                gates_s[0][row] = ga;
                gates_s[1][row] = gb;
            }
        } else {
            if (t > 0) layer2_step(t - 1, cur);   // pipelined one step behind
        }
        __syncthreads();   // gates ready
        if (tid < BPB * H1) {
            int bb = tid >> 6, j = tid & 63;
            float gi = gates_s[bb][j];
            float gf = gates_s[bb][H1 + j];
            float gc = gates_s[bb][2 * H1 + j];
            float go = gates_s[bb][3 * H1 + j];
            c_state = fmaf(gf, c_state, gi * gc);
            h1buf[cur ^ 1][bb][j] = go * tanh_f(c_state);
        }
        cur ^= 1;
    }
    __syncthreads();
    if (tid >= NGATE) layer2_step(T_STEPS - 1, cur);   // drain last layer2 step
}

extern "C" void kernel_launch(void* const* d_in, const int* in_sizes, int n_in,
                              void* d_out, int out_size) {
    (void)in_sizes; (void)n_in; (void)out_size;
    lstm2_fused_kernel<<<B_TOTAL / BPB, NTHREADS>>>(
        (const float*)d_in[0],
        (const float*)d_in[1], (const float*)d_in[2],
        (const float*)d_in[3], (const float*)d_in[4],
        (const float*)d_in[5], (const float*)d_in[6],
        (const float*)d_in[7], (const float*)d_in[8],
        (const float*)d_in[9], (const float*)d_in[10],
        (float*)d_out);
}

// round 3
// speedup vs baseline: 1.0127x; 1.0127x over previous
#include <cuda_runtime.h>

#define T_STEPS 256
#define IN_DIM 16
#define H1 64
#define BPB 4             // batches per block
#define NTHREADS 544      // 16 gate warps + 1 layer2 warp
#define B_TOTAL 4096

using u64 = unsigned long long;

__device__ __forceinline__ u64 pack2(float x, float y) {
    u64 r; asm("mov.b64 %0, {%1, %2};" : "=l"(r) : "f"(x), "f"(y)); return r;
}
__device__ __forceinline__ void unpack2(u64 v, float &x, float &y) {
    asm("mov.b64 {%0, %1}, %2;" : "=f"(x), "=f"(y) : "l"(v));
}
__device__ __forceinline__ u64 ffma2(u64 a, u64 b, u64 c) {
    u64 d; asm("fma.rn.f32x2 %0, %1, %2, %3;" : "=l"(d) : "l"(a), "l"(b), "l"(c)); return d;
}
__device__ __forceinline__ u64 addf2(u64 a, u64 b) {
    u64 d; asm("add.rn.f32x2 %0, %1, %2;" : "=l"(d) : "l"(a), "l"(b)); return d;
}
__device__ __forceinline__ float ex2f(float x){ float y; asm("ex2.approx.f32 %0, %1;" : "=f"(y) : "f"(x)); return y; }
__device__ __forceinline__ float rcpf(float x){ float y; asm("rcp.approx.f32 %0, %1;" : "=f"(y) : "f"(x)); return y; }
__device__ __forceinline__ float sigmoid_f(float x){ return rcpf(1.0f + ex2f(-1.4426950408889634f * x)); }
__device__ __forceinline__ float tanh_f(float x){ return 2.0f * rcpf(1.0f + ex2f(-2.8853900817779268f * x)) - 1.0f; }

__global__ void __launch_bounds__(NTHREADS, 1)
lstm2_fused_kernel(
    const float* __restrict__ x,
    const float* __restrict__ w_ih1, const float* __restrict__ w_hh1,
    const float* __restrict__ b_ih1, const float* __restrict__ b_hh1,
    const float* __restrict__ w_ih2, const float* __restrict__ w_hh2,
    const float* __restrict__ b_ih2, const float* __restrict__ b_hh2,
    const float* __restrict__ fc_w,  const float* __restrict__ fc_b,
    float* __restrict__ out)
{
    __shared__ float h1buf[2][BPB][H1];   // double-buffered layer1 hidden
    __shared__ float l2c[12];             // layer2 consts

    const int tid  = threadIdx.x;
    const int wid  = tid >> 5;
    const int lane = tid & 31;
    const int b0   = blockIdx.x * BPB;

    // prologue: zero both h buffers, stage layer2 consts
    if (tid < 2 * BPB * H1) ((float*)h1buf)[tid] = 0.0f;
    if (tid == 0) {
        #pragma unroll
        for (int g = 0; g < 4; ++g) {
            l2c[g]     = b_ih2[g] + b_hh2[g];
            l2c[4 + g] = w_hh2[g];
        }
        l2c[8] = fc_w[0];
        l2c[9] = fc_b[0];
    }

    if (wid < 16) {
        // ================= gate warps =================
        // lane = jsub*4 + q ; j = (wid&7)*8 + jsub ; bgroup = wid>>3 handles batches {2bg, 2bg+1}
        const int q    = lane & 3;
        const int jsub = lane >> 2;
        const int j    = (wid & 7) * 8 + jsub;
        const int bg   = wid >> 3;
        const int bi0  = bg * 2, bi1 = bg * 2 + 1;

        // weights: 4 gate rows (g*64+j), quarter columns
        u64 wih[4][2];
        u64 whh[4][8];
        #pragma unroll
        for (int g = 0; g < 4; ++g) {
            int row = g * H1 + j;
            ulonglong2 a = *(const ulonglong2*)(w_ih1 + row * IN_DIM + q * 4);
            wih[g][0] = a.x; wih[g][1] = a.y;
            #pragma unroll
            for (int k = 0; k < 4; ++k) {
                ulonglong2 b = *(const ulonglong2*)(w_hh1 + row * H1 + q * 16 + k * 4);
                whh[g][2*k] = b.x; whh[g][2*k+1] = b.y;
            }
        }
        const float bias = b_ih1[q * H1 + j] + b_hh1[q * H1 + j];

        // activation constants for my gate q (q==2 -> tanh, else sigmoid)
        const bool  isg  = (q == 2);
        const float kmul = isg ? -2.8853900817779268f : -1.4426950408889634f;
        const float smul = isg ? 2.0f : 1.0f;
        const float doff = isg ? -1.0f : 0.0f;

        float c0 = 0.0f, c1 = 0.0f;     // c-state (only q==0 lanes use)

        const float* xp0 = x + (size_t)(b0 + bi0) * (T_STEPS * IN_DIM) + q * 4;
        const float* xp1 = x + (size_t)(b0 + bi1) * (T_STEPS * IN_DIM) + q * 4;
        ulonglong2 xn0 = *(const ulonglong2*)(xp0);   // prefetch t=0
        ulonglong2 xn1 = *(const ulonglong2*)(xp1);

        __syncthreads();

        int cur = 0;
        #pragma unroll 1
        for (int t = 0; t < T_STEPS; ++t) {
            ulonglong2 xc0 = xn0, xc1 = xn1;
            int tn = (t + 1 < T_STEPS) ? t + 1 : t;
            xn0 = *(const ulonglong2*)(xp0 + tn * IN_DIM);   // prefetch next step
            xn1 = *(const ulonglong2*)(xp1 + tn * IN_DIM);

            const u64 z = 0ull;  // packed (0.0f, 0.0f)
            u64 acc[8];
            #pragma unroll
            for (int g = 0; g < 4; ++g) {
                u64 a0 = ffma2(wih[g][0], xc0.x, z);
                a0     = ffma2(wih[g][1], xc0.y, a0);
                u64 a1 = ffma2(wih[g][0], xc1.x, z);
                a1     = ffma2(wih[g][1], xc1.y, a1);
                acc[g]     = a0;
                acc[4 + g] = a1;
            }
            // hidden contribution, batch 0 then batch 1
            {
                const ulonglong2* hp = (const ulonglong2*)&h1buf[cur][bi0][q * 16];
                #pragma unroll
                for (int k = 0; k < 4; ++k) {
                    ulonglong2 hv = hp[k];
                    #pragma unroll
                    for (int g = 0; g < 4; ++g) {
                        acc[g] = ffma2(whh[g][2*k],   hv.x, acc[g]);
                        acc[g] = ffma2(whh[g][2*k+1], hv.y, acc[g]);
                    }
                }
            }
            {
                const ulonglong2* hp = (const ulonglong2*)&h1buf[cur][bi1][q * 16];
                #pragma unroll
                for (int k = 0; k < 4; ++k) {
                    ulonglong2 hv = hp[k];
                    #pragma unroll
                    for (int g = 0; g < 4; ++g) {
                        acc[4+g] = ffma2(whh[g][2*k],   hv.x, acc[4+g]);
                        acc[4+g] = ffma2(whh[g][2*k+1], hv.y, acc[4+g]);
                    }
                }
            }

            // per-batch: transpose-reduce over the 4 q-lanes, activate, update
            const int qb = q & 1;
            const int qh = (q >> 1) & 1;
            #pragma unroll
            for (int bb = 0; bb < 2; ++bb) {
                u64* a = &acc[bb * 4];
                // round 1 (xor 1): after this, lane holds gates {qb, 2+qb} half-sums
                u64 s0 = qb ? a[0] : a[1];
                u64 s1 = qb ? a[2] : a[3];
                u64 r0 = __shfl_xor_sync(0xffffffffu, s0, 1);
                u64 r1 = __shfl_xor_sync(0xffffffffu, s1, 1);
                u64 hs0 = addf2(qb ? a[1] : a[0], r0);
                u64 hs1 = addf2(qb ? a[3] : a[2], r1);
                // round 2 (xor 2): lane q ends with gate q total
                u64 s2 = qh ? hs0 : hs1;
                u64 r2 = __shfl_xor_sync(0xffffffffu, s2, 2);
                u64 tot = addf2(qh ? hs1 : hs0, r2);
                float tx, ty; unpack2(tot, tx, ty);
                float gsum = tx + ty + bias;
                // activation (gate q)
                float av = fmaf(smul, rcpf(1.0f + ex2f(kmul * gsum)), doff);
                // gather: lane0 of each quad gets i,f,g,o
                float a1v = __shfl_xor_sync(0xffffffffu, av, 1);
                float a2v = __shfl_xor_sync(0xffffffffu, av, 2);
                float a3v = __shfl_xor_sync(0xffffffffu, a1v, 2);
                if (q == 0) {
                    float& cst = bb ? c1 : c0;
                    cst = fmaf(a1v, cst, av * a2v);            // c = f*c + i*g
                    float hn = a3v * tanh_f(cst);               // h = o*tanh(c)
                    h1buf[cur ^ 1][bb ? bi1 : bi0][j] = hn;
                }
            }
            __syncthreads();
            cur ^= 1;
        }
    } else {
        // ================= layer2 + FC warp =================
        const int gg = lane >> 3;     // gate 0..3
        const int pp = lane & 7;      // 8-weight slice
        float w2[8];
        #pragma unroll
        for (int e = 0; e < 8; ++e) w2[e] = w_ih2[gg * H1 + pp * 8 + e];
        float h2s[BPB], c2s[BPB];
        #pragma unroll
        for (int bb = 0; bb < BPB; ++bb) { h2s[bb] = 0.0f; c2s[bb] = 0.0f; }

        __syncthreads();

        auto layer2_step = [&](int tt, int curbuf) {
            float p[BPB];
            #pragma unroll
            for (int bb = 0; bb < BPB; ++bb) {
                const float* hr = &h1buf[curbuf][bb][pp * 8];
                float s = 0.0f;
                #pragma unroll
                for (int e = 0; e < 8; ++e) s = fmaf(w2[e], hr[e], s);
                p[bb] = s;
            }
            #pragma unroll
            for (int bb = 0; bb < BPB; ++bb) {
                p[bb] += __shfl_xor_sync(0xffffffffu, p[bb], 1);
                p[bb] += __shfl_xor_sync(0xffffffffu, p[bb], 2);
                p[bb] += __shfl_xor_sync(0xffffffffu, p[bb], 4);
            }
            float s0[BPB], s1[BPB], s2[BPB], s3[BPB];
            #pragma unroll
            for (int bb = 0; bb < BPB; ++bb) {
                s0[bb] = __shfl_sync(0xffffffffu, p[bb], 0);
                s1[bb] = __shfl_sync(0xffffffffu, p[bb], 8);
                s2[bb] = __shfl_sync(0xffffffffu, p[bb], 16);
                s3[bb] = __shfl_sync(0xffffffffu, p[bb], 24);
            }
            if (lane == 0) {
                #pragma unroll
                for (int bb = 0; bb < BPB; ++bb) {
                    float hp = h2s[bb];
                    float i2 = sigmoid_f(s0[bb] + l2c[0] + l2c[4] * hp);
                    float f2 = sigmoid_f(s1[bb] + l2c[1] + l2c[5] * hp);
                    float g2 = tanh_f  (s2[bb] + l2c[2] + l2c[6] * hp);
                    float o2 = sigmoid_f(s3[bb] + l2c[3] + l2c[7] * hp);
                    float c2 = fmaf(f2, c2s[bb], i2 * g2);
                    c2s[bb] = c2;
                    float h2 = o2 * tanh_f(c2);
                    h2s[bb] = h2;
                    out[(size_t)(b0 + bb) * T_STEPS + tt] = fmaf(h2, l2c[8], l2c[9]);
                }
            }
        };

        int cur = 0;
        #pragma unroll 1
        for (int t = 0; t < T_STEPS; ++t) {
            if (t > 0) layer2_step(t - 1, cur);   // pipelined one step behind
            __syncthreads();
            cur ^= 1;
        }
        layer2_step(T_STEPS - 1, cur);            // drain (gate warps already exited; data is in smem)
    }
}

extern "C" void kernel_launch(void* const* d_in, const int* in_sizes, int n_in,
                              void* d_out, int out_size) {
    (void)in_sizes; (void)n_in; (void)out_size;
    lstm2_fused_kernel<<<B_TOTAL / BPB, NTHREADS>>>(
        (const float*)d_in[0],
        (const float*)d_in[1], (const float*)d_in[2],
        (const float*)d_in[3], (const float*)d_in[4],
        (const float*)d_in[5], (const float*)d_in[6],
        (const float*)d_in[7], (const float*)d_in[8],
        (const float*)d_in[9], (const float*)d_in[10],
        (float*)d_out);
}

// round 4
// speedup vs baseline: 1.0891x; 1.0755x over previous
#include <cuda_runtime.h>

#define T_STEPS 256
#define IN_DIM 16
#define TX (T_STEPS * IN_DIM)
#define H1 64
#define BPB 32            // batches per block
#define NPAIR 8           // batch-pairs per gate-warp group
#define NTHREADS 544      // 16 gate warps + 1 layer2 warp
#define NBLOCKS 128       // 4096 / 32 — single wave

using u64 = unsigned long long;

__device__ __forceinline__ void unpack2(u64 v, float &x, float &y) {
    asm("mov.b64 {%0, %1}, %2;" : "=f"(x), "=f"(y) : "l"(v));
}
__device__ __forceinline__ u64 ffma2(u64 a, u64 b, u64 c) {
    u64 d; asm("fma.rn.f32x2 %0, %1, %2, %3;" : "=l"(d) : "l"(a), "l"(b), "l"(c)); return d;
}
__device__ __forceinline__ u64 addf2(u64 a, u64 b) {
    u64 d; asm("add.rn.f32x2 %0, %1, %2;" : "=l"(d) : "l"(a), "l"(b)); return d;
}
__device__ __forceinline__ float ex2f(float x){ float y; asm("ex2.approx.f32 %0, %1;" : "=f"(y) : "f"(x)); return y; }
__device__ __forceinline__ float rcpf(float x){ float y; asm("rcp.approx.f32 %0, %1;" : "=f"(y) : "f"(x)); return y; }
__device__ __forceinline__ float sigmoid_f(float x){ return rcpf(1.0f + ex2f(-1.4426950408889634f * x)); }
__device__ __forceinline__ float tanh_f(float x){ return 2.0f * rcpf(1.0f + ex2f(-2.8853900817779268f * x)) - 1.0f; }

__global__ void __launch_bounds__(NTHREADS, 1)
lstm2_fused_kernel(
    const float* __restrict__ x,
    const float* __restrict__ w_ih1, const float* __restrict__ w_hh1,
    const float* __restrict__ b_ih1, const float* __restrict__ b_hh1,
    const float* __restrict__ w_ih2, const float* __restrict__ w_hh2,
    const float* __restrict__ b_ih2, const float* __restrict__ b_hh2,
    const float* __restrict__ fc_w,  const float* __restrict__ fc_b,
    float* __restrict__ out)
{
    __shared__ float h1buf[2][BPB][H1];   // 16 KB double-buffered hidden
    __shared__ float c_smem[BPB][H1];     // 8 KB cell state
    __shared__ float l2c[12];

    const int tid  = threadIdx.x;
    const int wid  = tid >> 5;
    const int lane = tid & 31;
    const int b0   = blockIdx.x * BPB;

    // zero h buffers + c
    for (int i = tid; i < (2 * BPB * H1 + BPB * H1); i += NTHREADS) {
        if (i < 2 * BPB * H1) ((float*)h1buf)[i] = 0.0f;
        else                  ((float*)c_smem)[i - 2 * BPB * H1] = 0.0f;
    }
    if (tid == 0) {
        #pragma unroll
        for (int g = 0; g < 4; ++g) {
            l2c[g]     = b_ih2[g] + b_hh2[g];
            l2c[4 + g] = w_hh2[g];
        }
        l2c[8] = fc_w[0];
        l2c[9] = fc_b[0];
    }

    if (wid < 16) {
        // ================= gate warps =================
        // lane = jsub*4 + q ; j = (wid&7)*8 + jsub ; group = wid>>3 -> batches [grp*16, grp*16+16)
        const int q    = lane & 3;
        const int jsub = lane >> 2;
        const int j    = (wid & 7) * 8 + jsub;
        const int grp  = wid >> 3;

        u64 wih[4][2];      // 4 gate rows, quarter of the 16 x-cols
        u64 whh[4][8];      // 4 gate rows, quarter of the 64 h-cols
        #pragma unroll
        for (int g = 0; g < 4; ++g) {
            int row = g * H1 + j;
            ulonglong2 a = *(const ulonglong2*)(w_ih1 + row * IN_DIM + q * 4);
            wih[g][0] = a.x; wih[g][1] = a.y;
            #pragma unroll
            for (int k = 0; k < 4; ++k) {
                ulonglong2 b = *(const ulonglong2*)(w_hh1 + row * H1 + q * 16 + k * 4);
                whh[g][2*k] = b.x; whh[g][2*k+1] = b.y;
            }
        }
        const float bias = b_ih1[q * H1 + j] + b_hh1[q * H1 + j];

        const bool  isg  = (q == 2);
        const float kmul = isg ? -2.8853900817779268f : -1.4426950408889634f;
        const float smul = isg ? 2.0f : 1.0f;
        const float doff = isg ? -1.0f : 0.0f;

        const float* xbase = x + (size_t)(b0 + grp * 16) * TX + q * 4;

        // prefetch pair 0, t=0
        ulonglong2 xn0 = *(const ulonglong2*)(xbase);
        ulonglong2 xn1 = *(const ulonglong2*)(xbase + TX);

        __syncthreads();

        int cur = 0;
        #pragma unroll 1
        for (int t = 0; t < T_STEPS; ++t) {
            #pragma unroll 1
            for (int p = 0; p < NPAIR; ++p) {
                ulonglong2 xc0 = xn0, xc1 = xn1;
                // prefetch next pair (wraps into next timestep's pair 0)
                {
                    int pn = p + 1, tn = t;
                    if (pn == NPAIR) { pn = 0; tn = (t + 1 < T_STEPS) ? t + 1 : t; }
                    const float* bp = xbase + pn * 2 * TX + tn * IN_DIM;
                    xn0 = *(const ulonglong2*)(bp);
                    xn1 = *(const ulonglong2*)(bp + TX);
                }
                const int bi0 = grp * 16 + p * 2;
                const int bi1 = bi0 + 1;

                const u64 z = 0ull;
                u64 acc[8];
                #pragma unroll
                for (int g = 0; g < 4; ++g) {
                    u64 a0 = ffma2(wih[g][0], xc0.x, z);
                    a0     = ffma2(wih[g][1], xc0.y, a0);
                    u64 a1 = ffma2(wih[g][0], xc1.x, z);
                    a1     = ffma2(wih[g][1], xc1.y, a1);
                    acc[g] = a0;  acc[4 + g] = a1;
                }
                {
                    const ulonglong2* hp = (const ulonglong2*)&h1buf[cur][bi0][q * 16];
                    #pragma unroll
                    for (int k = 0; k < 4; ++k) {
                        ulonglong2 hv = hp[k];
                        #pragma unroll
                        for (int g = 0; g < 4; ++g) {
                            acc[g] = ffma2(whh[g][2*k],   hv.x, acc[g]);
                            acc[g] = ffma2(whh[g][2*k+1], hv.y, acc[g]);
                        }
                    }
                }
                {
                    const ulonglong2* hp = (const ulonglong2*)&h1buf[cur][bi1][q * 16];
                    #pragma unroll
                    for (int k = 0; k < 4; ++k) {
                        ulonglong2 hv = hp[k];
                        #pragma unroll
                        for (int g = 0; g < 4; ++g) {
                            acc[4+g] = ffma2(whh[g][2*k],   hv.x, acc[4+g]);
                            acc[4+g] = ffma2(whh[g][2*k+1], hv.y, acc[4+g]);
                        }
                    }
                }

                // transpose-reduce over the 4 q-lanes, activate, update (per batch)
                const int qb = q & 1;
                const int qh = (q >> 1) & 1;
                #pragma unroll
                for (int bb = 0; bb < 2; ++bb) {
                    u64* a = &acc[bb * 4];
                    u64 s0 = qb ? a[0] : a[1];
                    u64 s1 = qb ? a[2] : a[3];
                    u64 r0 = __shfl_xor_sync(0xffffffffu, s0, 1);
                    u64 r1 = __shfl_xor_sync(0xffffffffu, s1, 1);
                    u64 hs0 = addf2(qb ? a[1] : a[0], r0);
                    u64 hs1 = addf2(qb ? a[3] : a[2], r1);
                    u64 s2 = qh ? hs0 : hs1;
                    u64 r2 = __shfl_xor_sync(0xffffffffu, s2, 2);
                    u64 tot = addf2(qh ? hs1 : hs0, r2);
                    float tx2, ty2; unpack2(tot, tx2, ty2);
                    float gsum = tx2 + ty2 + bias;
                    float av = fmaf(smul, rcpf(1.0f + ex2f(kmul * gsum)), doff);
                    float a1v = __shfl_xor_sync(0xffffffffu, av, 1);
                    float a2v = __shfl_xor_sync(0xffffffffu, av, 2);
                    float a3v = __shfl_xor_sync(0xffffffffu, a1v, 2);
                    if (q == 0) {
                        const int bi = bb ? bi1 : bi0;
                        float cst = c_smem[bi][j];
                        cst = fmaf(a1v, cst, av * a2v);        // c = f*c + i*g
                        c_smem[bi][j] = cst;
                        h1buf[cur ^ 1][bi][j] = a3v * tanh_f(cst);
                    }
                }
            }
            __syncthreads();
            cur ^= 1;
        }
    } else {
        // ================= layer2 + FC warp =================
        const int gg = lane >> 3;
        const int pp = lane & 7;
        float w2[8];
        #pragma unroll
        for (int e = 0; e < 8; ++e) w2[e] = w_ih2[gg * H1 + pp * 8 + e];
        float h2s[BPB], c2s[BPB];
        #pragma unroll
        for (int bb = 0; bb < BPB; ++bb) { h2s[bb] = 0.0f; c2s[bb] = 0.0f; }

        __syncthreads();

        auto layer2_step = [&](int tt, int curbuf) {
            #pragma unroll
            for (int cb = 0; cb < BPB; cb += 4) {
                float p[4];
                #pragma unroll
                for (int u = 0; u < 4; ++u) {
                    const float* hr = &h1buf[curbuf][cb + u][pp * 8];
                    float s = 0.0f;
                    #pragma unroll
                    for (int e = 0; e < 8; ++e) s = fmaf(w2[e], hr[e], s);
                    p[u] = s;
                }
                #pragma unroll
                for (int u = 0; u < 4; ++u) {
                    p[u] += __shfl_xor_sync(0xffffffffu, p[u], 1);
                    p[u] += __shfl_xor_sync(0xffffffffu, p[u], 2);
                    p[u] += __shfl_xor_sync(0xffffffffu, p[u], 4);
                }
                float s0[4], s1[4], s2[4], s3[4];
                #pragma unroll
                for (int u = 0; u < 4; ++u) {
                    s0[u] = __shfl_sync(0xffffffffu, p[u], 0);
                    s1[u] = __shfl_sync(0xffffffffu, p[u], 8);
                    s2[u] = __shfl_sync(0xffffffffu, p[u], 16);
                    s3[u] = __shfl_sync(0xffffffffu, p[u], 24);
                }
                if (lane == 0) {
                    #pragma unroll
                    for (int u = 0; u < 4; ++u) {
                        const int bb = cb + u;
                        float hp = h2s[bb];
                        float i2 = sigmoid_f(s0[u] + l2c[0] + l2c[4] * hp);
                        float f2 = sigmoid_f(s1[u] + l2c[1] + l2c[5] * hp);
                        float g2 = tanh_f  (s2[u] + l2c[2] + l2c[6] * hp);
                        float o2 = sigmoid_f(s3[u] + l2c[3] + l2c[7] * hp);
                        float c2 = fmaf(f2, c2s[bb], i2 * g2);
                        c2s[bb] = c2;
                        float h2 = o2 * tanh_f(c2);
                        h2s[bb] = h2;
                        out[(size_t)(b0 + bb) * T_STEPS + tt] = fmaf(h2, l2c[8], l2c[9]);
                    }
                }
            }
        };

        int cur = 0;
        #pragma unroll 1
        for (int t = 0; t < T_STEPS; ++t) {
            if (t > 0) layer2_step(t - 1, cur);   // pipelined one step behind
            __syncthreads();
            cur ^= 1;
        }
        layer2_step(T_STEPS - 1, cur);            // drain
    }
}

extern "C" void kernel_launch(void* const* d_in, const int* in_sizes, int n_in,
                              void* d_out, int out_size) {
    (void)in_sizes; (void)n_in; (void)out_size;
    lstm2_fused_kernel<<<NBLOCKS, NTHREADS>>>(
        (const float*)d_in[0],
        (const float*)d_in[1], (const float*)d_in[2],
        (const float*)d_in[3], (const float*)d_in[4],
        (const float*)d_in[5], (const float*)d_in[6],
        (const float*)d_in[7], (const float*)d_in[8],
        (const float*)d_in[9], (const float*)d_in[10],
        (float*)d_out);
}

// round 7
// speedup vs baseline: 1.1717x; 1.0759x over previous
#include <cuda_runtime.h>

#define T_STEPS 256
#define IN_DIM 16
#define TX (T_STEPS * IN_DIM)
#define H1 64
#define BPB 32            // batches per block
#define NPAIR 8           // batch-pairs per gate-warp group
#define NTHREADS 544      // 16 gate warps + 1 layer2 warp
#define NBLOCKS 128       // 4096/32 — single wave

using u64 = unsigned long long;

__device__ __forceinline__ void unpack2(u64 v, float &x, float &y) {
    asm("mov.b64 {%0, %1}, %2;" : "=f"(x), "=f"(y) : "l"(v));
}
__device__ __forceinline__ u64 ffma2(u64 a, u64 b, u64 c) {
    u64 d; asm("fma.rn.f32x2 %0, %1, %2, %3;" : "=l"(d) : "l"(a), "l"(b), "l"(c)); return d;
}
__device__ __forceinline__ float ex2f(float x){ float y; asm("ex2.approx.f32 %0, %1;" : "=f"(y) : "f"(x)); return y; }
__device__ __forceinline__ float rcpf(float x){ float y; asm("rcp.approx.f32 %0, %1;" : "=f"(y) : "f"(x)); return y; }
__device__ __forceinline__ float sigmoid_f(float x){ return rcpf(1.0f + ex2f(-1.4426950408889634f * x)); }
__device__ __forceinline__ float tanh_f(float x){ return 2.0f * rcpf(1.0f + ex2f(-2.8853900817779268f * x)) - 1.0f; }

__global__ void __launch_bounds__(NTHREADS, 1)
lstm2_fused_kernel(
    const float* __restrict__ x,
    const float* __restrict__ w_ih1, const float* __restrict__ w_hh1,
    const float* __restrict__ b_ih1, const float* __restrict__ b_hh1,
    const float* __restrict__ w_ih2, const float* __restrict__ w_hh2,
    const float* __restrict__ b_ih2, const float* __restrict__ b_hh2,
    const float* __restrict__ fc_w,  const float* __restrict__ fc_b,
    float* __restrict__ out)
{
    __shared__ float h1buf[2][BPB][H1];        // 16 KB double-buffered hidden
    __shared__ float part[16][2][4][36];       // 18 KB: [warp][bb][gate][jsub*4+q (+pad)]
    __shared__ float c_smem[BPB][H1];          // 8 KB cell state
    __shared__ float l2c[12];

    const int tid  = threadIdx.x;
    const int wid  = tid >> 5;
    const int lane = tid & 31;
    const int b0   = blockIdx.x * BPB;

    for (int i = tid; i < 3 * BPB * H1; i += NTHREADS) {
        if (i < 2 * BPB * H1) ((float*)h1buf)[i] = 0.0f;
        else                  ((float*)c_smem)[i - 2 * BPB * H1] = 0.0f;
    }
    if (tid == 0) {
        #pragma unroll
        for (int g = 0; g < 4; ++g) {
            l2c[g]     = b_ih2[g] + b_hh2[g];
            l2c[4 + g] = w_hh2[g];
        }
        l2c[8] = fc_w[0];
        l2c[9] = fc_b[0];
    }

    if (wid < 16) {
        // ================= gate warps =================
        // lane = jsub*4 + q ; j = (wid&7)*8 + jsub ; grp = wid>>3 -> batches [grp*16, grp*16+16)
        const int q    = lane & 3;
        const int jsub = lane >> 2;
        const int j    = (wid & 7) * 8 + jsub;
        const int grp  = wid >> 3;

        u64 wih[4][2];
        u64 whh[4][8];
        float bs[4];
        #pragma unroll
        for (int g = 0; g < 4; ++g) {
            int row = g * H1 + j;
            ulonglong2 a = *(const ulonglong2*)(w_ih1 + row * IN_DIM + q * 4);
            wih[g][0] = a.x; wih[g][1] = a.y;
            #pragma unroll
            for (int k = 0; k < 4; ++k) {
                ulonglong2 b = *(const ulonglong2*)(w_hh1 + row * H1 + q * 16 + k * 4);
                whh[g][2*k] = b.x; whh[g][2*k+1] = b.y;
            }
            bs[g] = b_ih1[row] + b_hh1[row];
        }

        float* mypart = &part[wid][0][0][0];          // [bb*144 + g*36 + jsub*4 + q]
        const float* xbase = x + (size_t)(b0 + grp * 16) * TX + q * 4;

        ulonglong2 xn0 = *(const ulonglong2*)(xbase);        // prefetch pair 0, t=0
        ulonglong2 xn1 = *(const ulonglong2*)(xbase + TX);

        __syncthreads();

        int cur = 0;
        #pragma unroll 1
        for (int t = 0; t < T_STEPS; ++t) {
            // flat prefetch index for next (pair, t): pi = p+1 within step, wraps to next t
            #pragma unroll 4
            for (int p = 0; p < NPAIR; ++p) {
                ulonglong2 xc0 = xn0, xc1 = xn1;
                {
                    int pn = p + 1;
                    int tn = t;
                    if (pn == NPAIR) { pn = 0; if (t + 1 < T_STEPS) tn = t + 1; }
                    const float* bp = xbase + pn * 2 * TX + tn * IN_DIM;
                    xn0 = *(const ulonglong2*)(bp);
                    xn1 = *(const ulonglong2*)(bp + TX);
                }
                const int bi0 = grp * 16 + p * 2;

                const u64 z = 0ull;
                u64 acc[8];
                #pragma unroll
                for (int g = 0; g < 4; ++g) {
                    u64 a0 = ffma2(wih[g][0], xc0.x, z);
                    a0     = ffma2(wih[g][1], xc0.y, a0);
                    u64 a1 = ffma2(wih[g][0], xc1.x, z);
                    a1     = ffma2(wih[g][1], xc1.y, a1);
                    acc[g] = a0;  acc[4 + g] = a1;
                }
                {
                    const ulonglong2* hp = (const ulonglong2*)&h1buf[cur][bi0][q * 16];
                    #pragma unroll
                    for (int k = 0; k < 4; ++k) {
                        ulonglong2 hv = hp[k];
                        #pragma unroll
                        for (int g = 0; g < 4; ++g) {
                            acc[g] = ffma2(whh[g][2*k],   hv.x, acc[g]);
                            acc[g] = ffma2(whh[g][2*k+1], hv.y, acc[g]);
                        }
                    }
                }
                {
                    const ulonglong2* hp = (const ulonglong2*)&h1buf[cur][bi0 + 1][q * 16];
                    #pragma unroll
                    for (int k = 0; k < 4; ++k) {
                        ulonglong2 hv = hp[k];
                        #pragma unroll
                        for (int g = 0; g < 4; ++g) {
                            acc[4+g] = ffma2(whh[g][2*k],   hv.x, acc[4+g]);
                            acc[4+g] = ffma2(whh[g][2*k+1], hv.y, acc[4+g]);
                        }
                    }
                }

                // conflict-free scalar STS of partial sums
                #pragma unroll
                for (int bb = 0; bb < 2; ++bb) {
                    #pragma unroll
                    for (int g = 0; g < 4; ++g) {
                        float ax, ay; unpack2(acc[bb * 4 + g], ax, ay);
                        mypart[bb * 144 + g * 36 + jsub * 4 + q] = ax + ay;
                    }
                }
                __syncwarp();

                // update: lanes q<2 finish (batch bi0+q, hidden j)
                if (q < 2) {
                    const int bi = bi0 + q;
                    float4 v0 = *(const float4*)&mypart[q * 144 + 0 * 36 + jsub * 4];
                    float4 v1 = *(const float4*)&mypart[q * 144 + 1 * 36 + jsub * 4];
                    float4 v2 = *(const float4*)&mypart[q * 144 + 2 * 36 + jsub * 4];
                    float4 v3 = *(const float4*)&mypart[q * 144 + 3 * 36 + jsub * 4];
                    float si = (v0.x + v0.y) + (v0.z + v0.w) + bs[0];
                    float sf = (v1.x + v1.y) + (v1.z + v1.w) + bs[1];
                    float sg = (v2.x + v2.y) + (v2.z + v2.w) + bs[2];
                    float so = (v3.x + v3.y) + (v3.z + v3.w) + bs[3];
                    float gi = sigmoid_f(si);
                    float gf = sigmoid_f(sf);
                    float gg = tanh_f(sg);
                    float go = sigmoid_f(so);
                    float c  = fmaf(gf, c_smem[bi][j], gi * gg);
                    c_smem[bi][j] = c;
                    h1buf[cur ^ 1][bi][j] = go * tanh_f(c);
                }
                __syncwarp();
            }
            __syncthreads();
            cur ^= 1;
        }
    } else {
        // ================= layer2 + FC warp =================
        const int gg = lane >> 3;
        const int pp = lane & 7;
        float w2[8];
        #pragma unroll
        for (int e = 0; e < 8; ++e) w2[e] = w_ih2[gg * H1 + pp * 8 + e];
        float h2s[BPB], c2s[BPB];
        #pragma unroll
        for (int bb = 0; bb < BPB; ++bb) { h2s[bb] = 0.0f; c2s[bb] = 0.0f; }

        __syncthreads();

        auto layer2_step = [&](int tt, int curbuf) {
            #pragma unroll 2
            for (int cb = 0; cb < BPB; cb += 4) {
                float p[4];
                #pragma unroll
                for (int u = 0; u < 4; ++u) {
                    const float* hr = &h1buf[curbuf][cb + u][pp * 8];
                    float s = 0.0f;
                    #pragma unroll
                    for (int e = 0; e < 8; ++e) s = fmaf(w2[e], hr[e], s);
                    p[u] = s;
                }
                #pragma unroll
                for (int u = 0; u < 4; ++u) {
                    p[u] += __shfl_xor_sync(0xffffffffu, p[u], 1);
                    p[u] += __shfl_xor_sync(0xffffffffu, p[u], 2);
                    p[u] += __shfl_xor_sync(0xffffffffu, p[u], 4);
                }
                float s0[4], s1[4], s2[4], s3[4];
                #pragma unroll
                for (int u = 0; u < 4; ++u) {
                    s0[u] = __shfl_sync(0xffffffffu, p[u], 0);
                    s1[u] = __shfl_sync(0xffffffffu, p[u], 8);
                    s2[u] = __shfl_sync(0xffffffffu, p[u], 16);
                    s3[u] = __shfl_sync(0xffffffffu, p[u], 24);
                }
                if (lane == 0) {
                    #pragma unroll
                    for (int u = 0; u < 4; ++u) {
                        const int bb = cb + u;
                        float hp = h2s[bb];
                        float i2 = sigmoid_f(s0[u] + l2c[0] + l2c[4] * hp);
                        float f2 = sigmoid_f(s1[u] + l2c[1] + l2c[5] * hp);
                        float g2 = tanh_f  (s2[u] + l2c[2] + l2c[6] * hp);
                        float o2 = sigmoid_f(s3[u] + l2c[3] + l2c[7] * hp);
                        float c2 = fmaf(f2, c2s[bb], i2 * g2);
                        c2s[bb] = c2;
                        float h2 = o2 * tanh_f(c2);
                        h2s[bb] = h2;
                        out[(size_t)(b0 + bb) * T_STEPS + tt] = fmaf(h2, l2c[8], l2c[9]);
                    }
                }
            }
        };

        int cur = 0;
        #pragma unroll 1
        for (int t = 0; t < T_STEPS; ++t) {
            if (t > 0) layer2_step(t - 1, cur);
            __syncthreads();
            cur ^= 1;
        }
        layer2_step(T_STEPS - 1, cur);
    }
}

extern "C" void kernel_launch(void* const* d_in, const int* in_sizes, int n_in,
                              void* d_out, int out_size) {
    (void)in_sizes; (void)n_in; (void)out_size;
    lstm2_fused_kernel<<<NBLOCKS, NTHREADS>>>(
        (const float*)d_in[0],
        (const float*)d_in[1], (const float*)d_in[2],
        (const float*)d_in[3], (const float*)d_in[4],
        (const float*)d_in[5], (const float*)d_in[6],
        (const float*)d_in[7], (const float*)d_in[8],
        (const float*)d_in[9], (const float*)d_in[10],
        (float*)d_out);
}